// round 2
// baseline (speedup 1.0000x reference)
#include <cuda_runtime.h>
#include <math.h>
#include <float.h>
#include <stdint.h>

#define BATCH 2
#define NPTS  4096
#define DIM   128
#define MD    16
#define KNBR  32
#define EDIM  530              // 2*EDGE_IN
#define NROWS (BATCH*NPTS)     // 8192

// ---------------- scratch (device globals; no allocations allowed) ----------------
__device__ float g_G [NROWS*EDIM];
__device__ float g_H [NROWS*EDIM];
__device__ float g_mi[NROWS*MD];
__device__ float g_X [NROWS*(DIM+MD)];
__device__ float g_Hn[NROWS*(2*DIM)];
__device__ float g_knn_dist[NROWS*KNBR];
__device__ int   g_knn_idx [NROWS*KNBR];

__device__ __forceinline__ float silu_f(float x){ return x / (1.0f + expf(-x)); }

// ---------------- kernel 1: exact KNN (matches jax.lax.top_k selection) ----------------
__global__ __launch_bounds__(256) void knn_kernel(const float* __restrict__ coors)
{
    __shared__ float sd[NPTS];
    __shared__ float rv[256];
    __shared__ int   ri[256];
    const int b = blockIdx.y, i = blockIdx.x, tid = threadIdx.x;
    const float* cb = coors + (size_t)b*NPTS*3;
    const float cx = cb[i*3+0], cy = cb[i*3+1], cz = cb[i*3+2];
    for (int j = tid; j < NPTS; j += 256) {
        float dx = cx - cb[j*3+0];
        float dy = cy - cb[j*3+1];
        float dz = cz - cb[j*3+2];
        // match reference arithmetic exactly: squares then (x2+y2)+z2, no FMA contraction
        float d = __fadd_rn(__fadd_rn(__fmul_rn(dx,dx), __fmul_rn(dy,dy)), __fmul_rn(dz,dz));
        sd[j] = d;
    }
    __syncthreads();
    const int gi = b*NPTS + i;
    for (int k = 0; k < KNBR; k++) {
        float best = FLT_MAX; int bi = NPTS;
        for (int j = tid; j < NPTS; j += 256) {
            float v = sd[j];
            if (v < best || (v == best && j < bi)) { best = v; bi = j; }
        }
        rv[tid] = best; ri[tid] = bi;
        __syncthreads();
        for (int s = 128; s > 0; s >>= 1) {
            if (tid < s) {
                float v2 = rv[tid+s]; int i2 = ri[tid+s];
                if (v2 < rv[tid] || (v2 == rv[tid] && i2 < ri[tid])) { rv[tid] = v2; ri[tid] = i2; }
            }
            __syncthreads();
        }
        if (tid == 0) {
            g_knn_idx [gi*KNBR + k] = ri[0];
            g_knn_dist[gi*KNBR + k] = rv[0];
            sd[ri[0]] = FLT_MAX;
        }
        __syncthreads();
    }
}

// ---------------- generic tiled SGEMM: C = act(A@B + bias) (+resid) ----------------
// A: MxK row-major, B: KxN row-major, M%64==0, K%16==0; N guarded.
__global__ __launch_bounds__(256) void sgemm_kernel(
    const float* __restrict__ A, const float* __restrict__ B,
    const float* __restrict__ bias, const float* __restrict__ resid,
    float* __restrict__ C, int M, int N, int K, int act)
{
    __shared__ float As[16][65];
    __shared__ float Bs[16][68];
    const int tid = threadIdx.x;
    const int tx = tid & 15, ty = tid >> 4;
    const int rowBase = blockIdx.y * 64, colBase = blockIdx.x * 64;
    const int aK = tid & 15, aRow = tid >> 4;
    const int bCol = tid & 63, bK = tid >> 6;
    float acc[4][4] = {};

    for (int k0 = 0; k0 < K; k0 += 16) {
        #pragma unroll
        for (int s = 0; s < 4; s++) {
            int r = aRow + s*16;
            As[aK][r] = A[(size_t)(rowBase + r)*K + k0 + aK];
        }
        #pragma unroll
        for (int s = 0; s < 4; s++) {
            int kk = bK + s*4;
            int col = colBase + bCol;
            Bs[kk][bCol] = (col < N) ? B[(size_t)(k0 + kk)*N + col] : 0.0f;
        }
        __syncthreads();
        #pragma unroll
        for (int kk = 0; kk < 16; kk++) {
            float a[4], bb[4];
            #pragma unroll
            for (int i = 0; i < 4; i++) a[i] = As[kk][ty*4 + i];
            #pragma unroll
            for (int j = 0; j < 4; j++) bb[j] = Bs[kk][tx*4 + j];
            #pragma unroll
            for (int i = 0; i < 4; i++)
                #pragma unroll
                for (int j = 0; j < 4; j++)
                    acc[i][j] = fmaf(a[i], bb[j], acc[i][j]);
        }
        __syncthreads();
    }
    #pragma unroll
    for (int i = 0; i < 4; i++) {
        int r = rowBase + ty*4 + i;
        #pragma unroll
        for (int j = 0; j < 4; j++) {
            int col = colBase + tx*4 + j;
            if (col < N) {
                float v = acc[i][j];
                if (bias)  v += bias[col];
                if (act)   v = silu_f(v);
                if (resid) v += resid[(size_t)r*N + col];
                C[(size_t)r*N + col] = v;
            }
        }
    }
}

// ---------------- edge kernel: pre1 = G[i]+H[j]+f9@Wf -> silu -> @We2 -> m_ij ... ----------------
// shared layout offsets (floats)
#define SM_W2T   0
#define SM_WF    (16*EDIM)
#define SM_G     (25*EDIM)
#define SM_F     (33*EDIM)
#define SM_WC1   (33*EDIM + 2304)
#define SM_BC1   (SM_WC1 + 1024)
#define SM_WC2   (SM_BC1 + 64)
#define SM_BE2   (SM_WC2 + 64)
#define SM_MIJ   (SM_BE2 + 16)
#define SM_MACC  (SM_MIJ + 128)
#define SM_CW    (SM_MACC + 128)
#define SM_IDX   (SM_CW + 256)
#define SM_TOTAL_FLOATS (SM_IDX + 256)
#define EDGE_SMEM_BYTES (SM_TOTAL_FLOATS * 4)

__device__ __forceinline__ void finish_edge(
    float* acc, int w, int lane, int e,
    float* sMij, float* sMacc, float* sCw,
    const float* sBe2, const float* sBc1, const float* sWc1, const float* sWc2,
    float bc2v)
{
    #pragma unroll
    for (int m = 0; m < 16; m++) {
        #pragma unroll
        for (int off = 16; off > 0; off >>= 1)
            acc[m] += __shfl_xor_sync(0xffffffffu, acc[m], off);
    }
    if (lane == 0) {
        #pragma unroll
        for (int m = 0; m < 16; m++) {
            float v = acc[m] + sBe2[m];
            sMij[w*16 + m] = v / (1.0f + expf(-v));
        }
    }
    __syncwarp();
    if (lane < 16) sMacc[w*16 + lane] += sMij[w*16 + lane];
    // coors MLP: 16 -> 64 (silu) -> 1 ; lane handles hidden units lane and lane+32
    float h0 = sBc1[lane], h1 = sBc1[lane + 32];
    #pragma unroll
    for (int m = 0; m < 16; m++) {
        float mm = sMij[w*16 + m];
        h0 = fmaf(mm, sWc1[m*64 + lane],      h0);
        h1 = fmaf(mm, sWc1[m*64 + lane + 32], h1);
    }
    h0 = h0 / (1.0f + expf(-h0));
    h1 = h1 / (1.0f + expf(-h1));
    float cw = h0 * sWc2[lane] + h1 * sWc2[lane + 32];
    #pragma unroll
    for (int off = 16; off > 0; off >>= 1)
        cw += __shfl_xor_sync(0xffffffffu, cw, off);
    if (lane == 0) sCw[w*32 + e] = cw + bc2v;
    __syncwarp();
}

__global__ __launch_bounds__(256, 2) void edge_kernel(
    const float* __restrict__ coors,
    const float* __restrict__ We2,  const float* __restrict__ be2,
    const float* __restrict__ Wc1,  const float* __restrict__ bc1,
    const float* __restrict__ Wc2,  const float* __restrict__ bc2,
    const float* __restrict__ We1,
    float* __restrict__ out_coors)
{
    extern __shared__ float sm[];
    float* sW2t = sm + SM_W2T;   // [16][530] We2 transposed
    float* sWf  = sm + SM_WF;    // [9][530]  fourier rows of We1
    float* sG   = sm + SM_G;     // [8][530]
    float* sF   = sm + SM_F;     // [8][32][9]
    float* sWc1 = sm + SM_WC1;   // [16][64]
    float* sBc1 = sm + SM_BC1;
    float* sWc2 = sm + SM_WC2;
    float* sBe2 = sm + SM_BE2;
    float* sMij = sm + SM_MIJ;   // [8][16]
    float* sMacc= sm + SM_MACC;  // [8][16]
    float* sCw  = sm + SM_CW;    // [8][32]
    int*   sIdx = (int*)(sm + SM_IDX); // [8][32]

    const int tid = threadIdx.x, lane = tid & 31, w = tid >> 5;
    const int b = blockIdx.y;
    const int i0 = blockIdx.x * 8;
    const int i  = i0 + w;
    const int gi = b*NPTS + i;

    // cooperative loads
    for (int t = tid; t < 16*EDIM; t += 256) { int x = t >> 4, m = t & 15; sW2t[m*EDIM + x] = We2[t]; }
    for (int t = tid; t < 9*EDIM;  t += 256) sWf[t] = We1[256*530 + t];
    for (int t = tid; t < 8*EDIM;  t += 256) sG[t]  = g_G[(size_t)(b*NPTS + i0)*EDIM + t];
    for (int t = tid; t < 1024;    t += 256) sWc1[t] = Wc1[t];
    if (tid < 64) { sBc1[tid] = bc1[tid]; sWc2[tid] = Wc2[tid]; }
    if (tid < 16) sBe2[tid] = be2[tid];
    if (tid < 128) sMacc[tid] = 0.0f;
    __syncthreads();

    const float bc2v = bc2[0];

    // per-edge fourier features (lane = edge)
    {
        const int e = lane;
        const int gk = gi*KNBR + e;
        const int j  = g_knn_idx[gk];
        sIdx[w*32 + e] = j;
        const float d = g_knn_dist[gk];
        float* fp = sF + (w*32 + e)*9;
        const float invs[4] = {1.0f, 0.5f, 0.25f, 0.125f};
        #pragma unroll
        for (int r = 0; r < 4; r++) {
            float sv, cv;
            sincosf(d * invs[r], &sv, &cv);
            fp[r] = sv; fp[4 + r] = cv;
        }
        fp[8] = d;
    }
    __syncwarp();

    const float* Hb = g_H + (size_t)b*NPTS*EDIM;

    #pragma unroll 1
    for (int pass = 0; pass < 16; pass++) {
        const int e0 = pass*2, e1 = e0 + 1;
        const int j0 = sIdx[w*32 + e0], j1 = sIdx[w*32 + e1];
        const float* H0 = Hb + (size_t)j0*EDIM;
        const float* H1 = Hb + (size_t)j1*EDIM;
        float f0[9], f1[9];
        #pragma unroll
        for (int r = 0; r < 9; r++) { f0[r] = sF[(w*32+e0)*9 + r]; f1[r] = sF[(w*32+e1)*9 + r]; }
        float acc0[16] = {}, acc1[16] = {};

        for (int c = 0; c < 17; c++) {
            int x = c*32 + lane;
            if (x < EDIM) {
                float g = sG[w*EDIM + x];
                float wf[9];
                #pragma unroll
                for (int r = 0; r < 9; r++) wf[r] = sWf[r*EDIM + x];
                float t0 = g + H0[x];
                float t1 = g + H1[x];
                #pragma unroll
                for (int r = 0; r < 9; r++) { t0 = fmaf(f0[r], wf[r], t0); t1 = fmaf(f1[r], wf[r], t1); }
                float s0 = t0 / (1.0f + expf(-t0));
                float s1 = t1 / (1.0f + expf(-t1));
                #pragma unroll
                for (int m = 0; m < 16; m++) {
                    float wv = sW2t[m*EDIM + x];
                    acc0[m] = fmaf(s0, wv, acc0[m]);
                    acc1[m] = fmaf(s1, wv, acc1[m]);
                }
            }
        }
        finish_edge(acc0, w, lane, e0, sMij, sMacc, sCw, sBe2, sBc1, sWc1, sWc2, bc2v);
        finish_edge(acc1, w, lane, e1, sMij, sMacc, sCw, sBe2, sBc1, sWc1, sWc2, bc2v);
    }

    // coors_out = sum_k cw_k * (coors_i - coors_jk) + coors_i ; lane = edge
    {
        const float ci0 = coors[(size_t)gi*3+0];
        const float ci1 = coors[(size_t)gi*3+1];
        const float ci2 = coors[(size_t)gi*3+2];
        const int j = sIdx[w*32 + lane];
        const float* cj = coors + ((size_t)b*NPTS + j)*3;
        const float cw = sCw[w*32 + lane];
        float rx = cw * (ci0 - cj[0]);
        float ry = cw * (ci1 - cj[1]);
        float rz = cw * (ci2 - cj[2]);
        #pragma unroll
        for (int off = 16; off > 0; off >>= 1) {
            rx += __shfl_xor_sync(0xffffffffu, rx, off);
            ry += __shfl_xor_sync(0xffffffffu, ry, off);
            rz += __shfl_xor_sync(0xffffffffu, rz, off);
        }
        if (lane == 0) {
            out_coors[(size_t)gi*3+0] = rx + ci0;
            out_coors[(size_t)gi*3+1] = ry + ci1;
            out_coors[(size_t)gi*3+2] = rz + ci2;
        }
        if (lane < 16) g_mi[(size_t)gi*MD + lane] = sMacc[w*16 + lane];
    }
}

// ---------------- assemble X = [feats | m_i] ----------------
__global__ void assemble_x(const float* __restrict__ feats)
{
    int t = blockIdx.x*blockDim.x + threadIdx.x;
    const int total = NROWS*(DIM+MD);
    if (t < total) {
        int r = t / (DIM+MD), c = t % (DIM+MD);
        g_X[t] = (c < DIM) ? feats[(size_t)r*DIM + c] : g_mi[(size_t)r*MD + (c - DIM)];
    }
}

// ---------------- host launcher ----------------
extern "C" void kernel_launch(void* const* d_in, const int* in_sizes, int n_in,
                              void* d_out, int out_size)
{
    const float* feats = (const float*)d_in[0];
    const float* coors = (const float*)d_in[1];
    const float* We1   = (const float*)d_in[2];
    const float* be1   = (const float*)d_in[3];
    const float* We2   = (const float*)d_in[4];
    const float* be2   = (const float*)d_in[5];
    const float* Wc1   = (const float*)d_in[6];
    const float* bc1   = (const float*)d_in[7];
    const float* Wc2   = (const float*)d_in[8];
    const float* bc2   = (const float*)d_in[9];
    const float* Wn1   = (const float*)d_in[10];
    const float* bn1   = (const float*)d_in[11];
    const float* Wn2   = (const float*)d_in[12];
    const float* bn2   = (const float*)d_in[13];

    float* out       = (float*)d_out;
    float* out_node  = out;                              // (b, n, 128)
    float* out_coors = out + (size_t)NROWS*DIM;          // (b, n, 3)

    float *G, *H, *X, *Hn;
    cudaGetSymbolAddress((void**)&G,  g_G);
    cudaGetSymbolAddress((void**)&H,  g_H);
    cudaGetSymbolAddress((void**)&X,  g_X);
    cudaGetSymbolAddress((void**)&Hn, g_Hn);

    // 1) KNN
    knn_kernel<<<dim3(NPTS, BATCH), 256>>>(coors);

    // 2) G = feats @ We1[0:128] + be1 ; H = feats @ We1[128:256]
    dim3 gGH((EDIM + 63)/64, NROWS/64);
    sgemm_kernel<<<gGH, 256>>>(feats, We1,            be1,     nullptr, G, NROWS, EDIM, DIM, 0);
    sgemm_kernel<<<gGH, 256>>>(feats, We1 + 128*530,  nullptr, nullptr, H, NROWS, EDIM, DIM, 0);

    // 3) edge kernel
    cudaFuncSetAttribute(edge_kernel, cudaFuncAttributeMaxDynamicSharedMemorySize, EDGE_SMEM_BYTES);
    edge_kernel<<<dim3(NPTS/8, BATCH), 256, EDGE_SMEM_BYTES>>>(
        coors, We2, be2, Wc1, bc1, Wc2, bc2, We1, out_coors);

    // 4) node MLP
    {
        int total = NROWS*(DIM+MD);
        assemble_x<<<(total + 255)/256, 256>>>(feats);
    }
    sgemm_kernel<<<dim3((2*DIM + 63)/64, NROWS/64), 256>>>(X,  Wn1, bn1, nullptr, Hn,       NROWS, 2*DIM, DIM+MD, 1);
    sgemm_kernel<<<dim3((DIM   + 63)/64, NROWS/64), 256>>>(Hn, Wn2, bn2, feats,   out_node, NROWS, DIM,   2*DIM,  0);
}

// round 3
// speedup vs baseline: 1.2723x; 1.2723x over previous
#include <cuda_runtime.h>
#include <math.h>
#include <float.h>
#include <stdint.h>

#define BATCH 2
#define NPTS  4096
#define DIM   128
#define MD    16
#define KNBR  32
#define EDIM  530              // 2*EDGE_IN
#define NROWS (BATCH*NPTS)     // 8192

// ---------------- scratch (device globals; no allocations allowed) ----------------
__device__ float g_G [NROWS*EDIM];
__device__ float g_H [NROWS*EDIM];
__device__ float g_mi[NROWS*MD];
__device__ float g_X [NROWS*(DIM+MD)];
__device__ float g_Hn[NROWS*(2*DIM)];
__device__ float g_knn_dist[NROWS*KNBR];
__device__ int   g_knn_idx [NROWS*KNBR];

// fast SiLU: MUFU.EX2 + MUFU.RCP, rel err ~1e-6 (threshold is 1e-3)
__device__ __forceinline__ float silu_f(float x){
    return __fdividef(x, 1.0f + __expf(-x));
}

// ---------------- kernel 1: exact KNN, warp-register top-k ----------------
// Distance arithmetic matches the reference bit-for-bit; selection comparator is
// (dist, index) lexicographic which matches jax.lax.top_k tie-breaking.
__global__ __launch_bounds__(256) void knn_kernel(const float* __restrict__ coors)
{
    __shared__ float cd[256];
    __shared__ int   ci[256];
    const int b = blockIdx.y, i = blockIdx.x, tid = threadIdx.x;
    const int lane = tid & 31, w = tid >> 5;
    const float* cb = coors + (size_t)b*NPTS*3;
    const float cx = cb[i*3+0], cy = cb[i*3+1], cz = cb[i*3+2];

    // each warp owns 512 points; each lane holds 16 distances in registers
    float dl[16];
    const int jbase = w*512 + lane;
    #pragma unroll
    for (int t = 0; t < 16; t++) {
        int j = jbase + t*32;
        float dx = cx - cb[j*3+0];
        float dy = cy - cb[j*3+1];
        float dz = cz - cb[j*3+2];
        dl[t] = __fadd_rn(__fadd_rn(__fmul_rn(dx,dx), __fmul_rn(dy,dy)), __fmul_rn(dz,dz));
    }

    // stage 1: per-warp top-32 (shfl-only)
    for (int k = 0; k < KNBR; k++) {
        float best = FLT_MAX; int bt = 0;
        #pragma unroll
        for (int t = 0; t < 16; t++)           // ascending t = ascending j; strict < keeps smallest j on ties
            if (dl[t] < best) { best = dl[t]; bt = t; }
        int bj = jbase + bt*32;
        float v = best; int jj = (best < FLT_MAX) ? bj : 0x7fffffff;
        #pragma unroll
        for (int off = 16; off > 0; off >>= 1) {
            float v2 = __shfl_xor_sync(0xffffffffu, v, off);
            int   j2 = __shfl_xor_sync(0xffffffffu, jj, off);
            if (v2 < v || (v2 == v && j2 < jj)) { v = v2; jj = j2; }
        }
        if (jj == bj) dl[bt] = FLT_MAX;        // unique winner (j unique per lane)
        if (lane == 0) { cd[w*32 + k] = v; ci[w*32 + k] = jj; }
    }
    __syncthreads();

    // stage 2: warp 0 merges 256 candidates -> global top-32
    if (w == 0) {
        float md[8]; int mj[8];
        #pragma unroll
        for (int t = 0; t < 8; t++) { md[t] = cd[lane + t*32]; mj[t] = ci[lane + t*32]; }
        const int gi = b*NPTS + i;
        for (int k = 0; k < KNBR; k++) {
            float best = FLT_MAX; int bj = 0x7fffffff; int bt = 0;
            #pragma unroll
            for (int t = 0; t < 8; t++)
                if (md[t] < best || (md[t] == best && mj[t] < bj)) { best = md[t]; bj = mj[t]; bt = t; }
            float v = best; int jj = bj;
            #pragma unroll
            for (int off = 16; off > 0; off >>= 1) {
                float v2 = __shfl_xor_sync(0xffffffffu, v, off);
                int   j2 = __shfl_xor_sync(0xffffffffu, jj, off);
                if (v2 < v || (v2 == v && j2 < jj)) { v = v2; jj = j2; }
            }
            if (jj == bj && best == v) md[bt] = FLT_MAX;
            if (lane == 0) { g_knn_dist[gi*KNBR + k] = v; g_knn_idx[gi*KNBR + k] = jj; }
        }
    }
}

// ---------------- generic tiled SGEMM: C = act(A@B + bias) (+resid) ----------------
__global__ __launch_bounds__(256) void sgemm_kernel(
    const float* __restrict__ A, const float* __restrict__ B,
    const float* __restrict__ bias, const float* __restrict__ resid,
    float* __restrict__ C, int M, int N, int K, int act)
{
    __shared__ float As[16][65];
    __shared__ float Bs[16][68];
    const int tid = threadIdx.x;
    const int tx = tid & 15, ty = tid >> 4;
    const int rowBase = blockIdx.y * 64, colBase = blockIdx.x * 64;
    const int aK = tid & 15, aRow = tid >> 4;
    const int bCol = tid & 63, bK = tid >> 6;
    float acc[4][4] = {};

    for (int k0 = 0; k0 < K; k0 += 16) {
        #pragma unroll
        for (int s = 0; s < 4; s++) {
            int r = aRow + s*16;
            As[aK][r] = A[(size_t)(rowBase + r)*K + k0 + aK];
        }
        #pragma unroll
        for (int s = 0; s < 4; s++) {
            int kk = bK + s*4;
            int col = colBase + bCol;
            Bs[kk][bCol] = (col < N) ? B[(size_t)(k0 + kk)*N + col] : 0.0f;
        }
        __syncthreads();
        #pragma unroll
        for (int kk = 0; kk < 16; kk++) {
            float a[4], bb[4];
            #pragma unroll
            for (int i = 0; i < 4; i++) a[i] = As[kk][ty*4 + i];
            #pragma unroll
            for (int j = 0; j < 4; j++) bb[j] = Bs[kk][tx*4 + j];
            #pragma unroll
            for (int i = 0; i < 4; i++)
                #pragma unroll
                for (int j = 0; j < 4; j++)
                    acc[i][j] = fmaf(a[i], bb[j], acc[i][j]);
        }
        __syncthreads();
    }
    #pragma unroll
    for (int i = 0; i < 4; i++) {
        int r = rowBase + ty*4 + i;
        #pragma unroll
        for (int j = 0; j < 4; j++) {
            int col = colBase + tx*4 + j;
            if (col < N) {
                float v = acc[i][j];
                if (bias)  v += bias[col];
                if (act)   v = silu_f(v);
                if (resid) v += resid[(size_t)r*N + col];
                C[(size_t)r*N + col] = v;
            }
        }
    }
}

// ---------------- edge kernel ----------------
// shared layout offsets (floats)
#define SM_W2T   0
#define SM_WF    (16*EDIM)
#define SM_F     (25*EDIM)
#define SM_WC1   (25*EDIM + 2304)
#define SM_BC1   (SM_WC1 + 1024)
#define SM_WC2   (SM_BC1 + 64)
#define SM_BE2   (SM_WC2 + 64)
#define SM_MIJ   (SM_BE2 + 16)
#define SM_MACC  (SM_MIJ + 128)
#define SM_CW    (SM_MACC + 128)
#define SM_IDX   (SM_CW + 256)
#define SM_TOTAL_FLOATS (SM_IDX + 256)
#define EDGE_SMEM_BYTES (SM_TOTAL_FLOATS * 4)

__device__ __forceinline__ void finish_edge(
    float* acc, int w, int lane, int e,
    float* sMij, float* sMacc, float* sCw,
    const float* sBe2, const float* sBc1, const float* sWc1, const float* sWc2,
    float bc2v)
{
    #pragma unroll
    for (int m = 0; m < 16; m++) {
        #pragma unroll
        for (int off = 16; off > 0; off >>= 1)
            acc[m] += __shfl_xor_sync(0xffffffffu, acc[m], off);
    }
    if (lane == 0) {
        #pragma unroll
        for (int m = 0; m < 16; m++) {
            float v = acc[m] + sBe2[m];
            sMij[w*16 + m] = silu_f(v);
        }
    }
    __syncwarp();
    if (lane < 16) sMacc[w*16 + lane] += sMij[w*16 + lane];
    // coors MLP: 16 -> 64 (silu) -> 1 ; lane handles hidden units lane and lane+32
    float h0 = sBc1[lane], h1 = sBc1[lane + 32];
    #pragma unroll
    for (int m = 0; m < 16; m++) {
        float mm = sMij[w*16 + m];
        h0 = fmaf(mm, sWc1[m*64 + lane],      h0);
        h1 = fmaf(mm, sWc1[m*64 + lane + 32], h1);
    }
    h0 = silu_f(h0);
    h1 = silu_f(h1);
    float cw = h0 * sWc2[lane] + h1 * sWc2[lane + 32];
    #pragma unroll
    for (int off = 16; off > 0; off >>= 1)
        cw += __shfl_xor_sync(0xffffffffu, cw, off);
    if (lane == 0) sCw[w*32 + e] = cw + bc2v;
    __syncwarp();
}

__global__ __launch_bounds__(256, 2) void edge_kernel(
    const float* __restrict__ coors,
    const float* __restrict__ We2,  const float* __restrict__ be2,
    const float* __restrict__ Wc1,  const float* __restrict__ bc1,
    const float* __restrict__ Wc2,  const float* __restrict__ bc2,
    const float* __restrict__ We1,
    float* __restrict__ out_coors)
{
    extern __shared__ float sm[];
    float* sW2t = sm + SM_W2T;   // [16][530] We2 transposed
    float* sWf  = sm + SM_WF;    // [9][530]  fourier rows of We1
    float* sF   = sm + SM_F;     // [8][32][9]
    float* sWc1 = sm + SM_WC1;   // [16][64]
    float* sBc1 = sm + SM_BC1;
    float* sWc2 = sm + SM_WC2;
    float* sBe2 = sm + SM_BE2;
    float* sMij = sm + SM_MIJ;   // [8][16]
    float* sMacc= sm + SM_MACC;  // [8][16]
    float* sCw  = sm + SM_CW;    // [8][32]
    int*   sIdx = (int*)(sm + SM_IDX); // [8][32]

    const int tid = threadIdx.x, lane = tid & 31, w = tid >> 5;
    const int b = blockIdx.y;
    const int i0 = blockIdx.x * 8;
    const int i  = i0 + w;
    const int gi = b*NPTS + i;

    // cooperative loads
    for (int t = tid; t < 16*EDIM; t += 256) { int x = t >> 4, m = t & 15; sW2t[m*EDIM + x] = We2[t]; }
    for (int t = tid; t < 9*EDIM;  t += 256) sWf[t] = We1[256*530 + t];
    for (int t = tid; t < 1024;    t += 256) sWc1[t] = Wc1[t];
    if (tid < 64) { sBc1[tid] = bc1[tid]; sWc2[tid] = Wc2[tid]; }
    if (tid < 16) sBe2[tid] = be2[tid];
    if (tid < 128) sMacc[tid] = 0.0f;
    __syncthreads();

    const float bc2v = bc2[0];

    // per-edge fourier features (lane = edge)
    {
        const int e = lane;
        const int gk = gi*KNBR + e;
        const int j  = g_knn_idx[gk];
        sIdx[w*32 + e] = j;
        const float d = g_knn_dist[gk];
        float* fp = sF + (w*32 + e)*9;
        const float invs[4] = {1.0f, 0.5f, 0.25f, 0.125f};
        #pragma unroll
        for (int r = 0; r < 4; r++) {
            float sv, cv;
            sincosf(d * invs[r], &sv, &cv);
            fp[r] = sv; fp[4 + r] = cv;
        }
        fp[8] = d;
    }
    __syncwarp();

    const float* Hb = g_H + (size_t)b*NPTS*EDIM;
    const float* Gp = g_G + (size_t)gi*EDIM;    // node's own G row: L1-resident (2KB/warp)

    #pragma unroll 1
    for (int pass = 0; pass < 16; pass++) {
        const int e0 = pass*2, e1 = e0 + 1;
        const int j0 = sIdx[w*32 + e0], j1 = sIdx[w*32 + e1];
        const float* H0 = Hb + (size_t)j0*EDIM;
        const float* H1 = Hb + (size_t)j1*EDIM;
        float f0[9], f1[9];
        #pragma unroll
        for (int r = 0; r < 9; r++) { f0[r] = sF[(w*32+e0)*9 + r]; f1[r] = sF[(w*32+e1)*9 + r]; }
        float acc0[16] = {}, acc1[16] = {};

        for (int c = 0; c < 17; c++) {
            int x = c*32 + lane;
            if (x < EDIM) {
                float g = __ldg(&Gp[x]);
                float wf[9];
                #pragma unroll
                for (int r = 0; r < 9; r++) wf[r] = sWf[r*EDIM + x];
                float t0 = g + H0[x];
                float t1 = g + H1[x];
                #pragma unroll
                for (int r = 0; r < 9; r++) { t0 = fmaf(f0[r], wf[r], t0); t1 = fmaf(f1[r], wf[r], t1); }
                float s0 = silu_f(t0);
                float s1 = silu_f(t1);
                #pragma unroll
                for (int m = 0; m < 16; m++) {
                    float wv = sW2t[m*EDIM + x];
                    acc0[m] = fmaf(s0, wv, acc0[m]);
                    acc1[m] = fmaf(s1, wv, acc1[m]);
                }
            }
        }
        finish_edge(acc0, w, lane, e0, sMij, sMacc, sCw, sBe2, sBc1, sWc1, sWc2, bc2v);
        finish_edge(acc1, w, lane, e1, sMij, sMacc, sCw, sBe2, sBc1, sWc1, sWc2, bc2v);
    }

    // coors_out = sum_k cw_k * (coors_i - coors_jk) + coors_i ; lane = edge
    {
        const float ci0 = coors[(size_t)gi*3+0];
        const float ci1 = coors[(size_t)gi*3+1];
        const float ci2 = coors[(size_t)gi*3+2];
        const int j = sIdx[w*32 + lane];
        const float* cj = coors + ((size_t)b*NPTS + j)*3;
        const float cw = sCw[w*32 + lane];
        float rx = cw * (ci0 - cj[0]);
        float ry = cw * (ci1 - cj[1]);
        float rz = cw * (ci2 - cj[2]);
        #pragma unroll
        for (int off = 16; off > 0; off >>= 1) {
            rx += __shfl_xor_sync(0xffffffffu, rx, off);
            ry += __shfl_xor_sync(0xffffffffu, ry, off);
            rz += __shfl_xor_sync(0xffffffffu, rz, off);
        }
        if (lane == 0) {
            out_coors[(size_t)gi*3+0] = rx + ci0;
            out_coors[(size_t)gi*3+1] = ry + ci1;
            out_coors[(size_t)gi*3+2] = rz + ci2;
        }
        if (lane < 16) g_mi[(size_t)gi*MD + lane] = sMacc[w*16 + lane];
    }
}

// ---------------- assemble X = [feats | m_i] ----------------
__global__ void assemble_x(const float* __restrict__ feats)
{
    int t = blockIdx.x*blockDim.x + threadIdx.x;
    const int total = NROWS*(DIM+MD);
    if (t < total) {
        int r = t / (DIM+MD), c = t % (DIM+MD);
        g_X[t] = (c < DIM) ? feats[(size_t)r*DIM + c] : g_mi[(size_t)r*MD + (c - DIM)];
    }
}

// ---------------- host launcher ----------------
extern "C" void kernel_launch(void* const* d_in, const int* in_sizes, int n_in,
                              void* d_out, int out_size)
{
    const float* feats = (const float*)d_in[0];
    const float* coors = (const float*)d_in[1];
    const float* We1   = (const float*)d_in[2];
    const float* be1   = (const float*)d_in[3];
    const float* We2   = (const float*)d_in[4];
    const float* be2   = (const float*)d_in[5];
    const float* Wc1   = (const float*)d_in[6];
    const float* bc1   = (const float*)d_in[7];
    const float* Wc2   = (const float*)d_in[8];
    const float* bc2   = (const float*)d_in[9];
    const float* Wn1   = (const float*)d_in[10];
    const float* bn1   = (const float*)d_in[11];
    const float* Wn2   = (const float*)d_in[12];
    const float* bn2   = (const float*)d_in[13];

    float* out       = (float*)d_out;
    float* out_node  = out;                              // (b, n, 128)
    float* out_coors = out + (size_t)NROWS*DIM;          // (b, n, 3)

    float *G, *H, *X, *Hn;
    cudaGetSymbolAddress((void**)&G,  g_G);
    cudaGetSymbolAddress((void**)&H,  g_H);
    cudaGetSymbolAddress((void**)&X,  g_X);
    cudaGetSymbolAddress((void**)&Hn, g_Hn);

    // 1) KNN
    knn_kernel<<<dim3(NPTS, BATCH), 256>>>(coors);

    // 2) G = feats @ We1[0:128] + be1 ; H = feats @ We1[128:256]
    dim3 gGH((EDIM + 63)/64, NROWS/64);
    sgemm_kernel<<<gGH, 256>>>(feats, We1,            be1,     nullptr, G, NROWS, EDIM, DIM, 0);
    sgemm_kernel<<<gGH, 256>>>(feats, We1 + 128*530,  nullptr, nullptr, H, NROWS, EDIM, DIM, 0);

    // 3) edge kernel
    cudaFuncSetAttribute(edge_kernel, cudaFuncAttributeMaxDynamicSharedMemorySize, EDGE_SMEM_BYTES);
    edge_kernel<<<dim3(NPTS/8, BATCH), 256, EDGE_SMEM_BYTES>>>(
        coors, We2, be2, Wc1, bc1, Wc2, bc2, We1, out_coors);

    // 4) node MLP
    {
        int total = NROWS*(DIM+MD);
        assemble_x<<<(total + 255)/256, 256>>>(feats);
    }
    sgemm_kernel<<<dim3((2*DIM + 63)/64, NROWS/64), 256>>>(X,  Wn1, bn1, nullptr, Hn,       NROWS, 2*DIM, DIM+MD, 1);
    sgemm_kernel<<<dim3((DIM   + 63)/64, NROWS/64), 256>>>(Hn, Wn2, bn2, feats,   out_node, NROWS, DIM,   2*DIM,  0);
}

// round 4
// speedup vs baseline: 1.4720x; 1.1569x over previous
#include <cuda_runtime.h>
#include <math.h>
#include <float.h>
#include <stdint.h>

#define BATCH 2
#define NPTS  4096
#define DIM   128
#define MD    16
#define KNBR  32
#define EDIM  530              // 2*EDGE_IN
#define EDIMP 544              // padded to 17*32 (float4-tileable)
#define NROWS (BATCH*NPTS)     // 8192

// ---------------- scratch (device globals; zero-initialized at load) ----------------
__device__ float g_G [NROWS*EDIMP];   // padded cols stay zero (never written)
__device__ float g_H [NROWS*EDIMP];
__device__ float g_mi[NROWS*MD];
__device__ float g_X [NROWS*(DIM+MD)];
__device__ float g_Hn[NROWS*(2*DIM)];
__device__ float g_knn_dist[NROWS*KNBR];
__device__ int   g_knn_idx [NROWS*KNBR];

// fast SiLU: MUFU.EX2 + MUFU.RCP, rel err ~1e-6 (threshold is 1e-3)
__device__ __forceinline__ float silu_f(float x){
    return __fdividef(x, 1.0f + __expf(-x));
}

// ---------------- kernel 1: exact KNN, warp-register top-k ----------------
__global__ __launch_bounds__(256) void knn_kernel(const float* __restrict__ coors)
{
    __shared__ float cd[256];
    __shared__ int   ci[256];
    const int b = blockIdx.y, i = blockIdx.x, tid = threadIdx.x;
    const int lane = tid & 31, w = tid >> 5;
    const float* cb = coors + (size_t)b*NPTS*3;
    const float cx = cb[i*3+0], cy = cb[i*3+1], cz = cb[i*3+2];

    float dl[16];
    const int jbase = w*512 + lane;
    #pragma unroll
    for (int t = 0; t < 16; t++) {
        int j = jbase + t*32;
        float dx = cx - cb[j*3+0];
        float dy = cy - cb[j*3+1];
        float dz = cz - cb[j*3+2];
        dl[t] = __fadd_rn(__fadd_rn(__fmul_rn(dx,dx), __fmul_rn(dy,dy)), __fmul_rn(dz,dz));
    }

    for (int k = 0; k < KNBR; k++) {
        float best = FLT_MAX; int bt = 0;
        #pragma unroll
        for (int t = 0; t < 16; t++)
            if (dl[t] < best) { best = dl[t]; bt = t; }
        int bj = jbase + bt*32;
        float v = best; int jj = (best < FLT_MAX) ? bj : 0x7fffffff;
        #pragma unroll
        for (int off = 16; off > 0; off >>= 1) {
            float v2 = __shfl_xor_sync(0xffffffffu, v, off);
            int   j2 = __shfl_xor_sync(0xffffffffu, jj, off);
            if (v2 < v || (v2 == v && j2 < jj)) { v = v2; jj = j2; }
        }
        if (jj == bj) dl[bt] = FLT_MAX;
        if (lane == 0) { cd[w*32 + k] = v; ci[w*32 + k] = jj; }
    }
    __syncthreads();

    if (w == 0) {
        float md[8]; int mj[8];
        #pragma unroll
        for (int t = 0; t < 8; t++) { md[t] = cd[lane + t*32]; mj[t] = ci[lane + t*32]; }
        const int gi = b*NPTS + i;
        for (int k = 0; k < KNBR; k++) {
            float best = FLT_MAX; int bj = 0x7fffffff; int bt = 0;
            #pragma unroll
            for (int t = 0; t < 8; t++)
                if (md[t] < best || (md[t] == best && mj[t] < bj)) { best = md[t]; bj = mj[t]; bt = t; }
            float v = best; int jj = bj;
            #pragma unroll
            for (int off = 16; off > 0; off >>= 1) {
                float v2 = __shfl_xor_sync(0xffffffffu, v, off);
                int   j2 = __shfl_xor_sync(0xffffffffu, jj, off);
                if (v2 < v || (v2 == v && j2 < jj)) { v = v2; jj = j2; }
            }
            if (jj == bj && best == v) md[bt] = FLT_MAX;
            if (lane == 0) { g_knn_dist[gi*KNBR + k] = v; g_knn_idx[gi*KNBR + k] = jj; }
        }
    }
}

// ---------------- generic tiled SGEMM: C = act(A@B + bias) (+resid), ldc ----------------
__global__ __launch_bounds__(256) void sgemm_kernel(
    const float* __restrict__ A, const float* __restrict__ B,
    const float* __restrict__ bias, const float* __restrict__ resid,
    float* __restrict__ C, int M, int N, int K, int act, int ldc)
{
    __shared__ float As[16][65];
    __shared__ float Bs[16][68];
    const int tid = threadIdx.x;
    const int tx = tid & 15, ty = tid >> 4;
    const int rowBase = blockIdx.y * 64, colBase = blockIdx.x * 64;
    const int aK = tid & 15, aRow = tid >> 4;
    const int bCol = tid & 63, bK = tid >> 6;
    float acc[4][4] = {};

    for (int k0 = 0; k0 < K; k0 += 16) {
        #pragma unroll
        for (int s = 0; s < 4; s++) {
            int r = aRow + s*16;
            As[aK][r] = A[(size_t)(rowBase + r)*K + k0 + aK];
        }
        #pragma unroll
        for (int s = 0; s < 4; s++) {
            int kk = bK + s*4;
            int col = colBase + bCol;
            Bs[kk][bCol] = (col < N) ? B[(size_t)(k0 + kk)*N + col] : 0.0f;
        }
        __syncthreads();
        #pragma unroll
        for (int kk = 0; kk < 16; kk++) {
            float a[4], bb[4];
            #pragma unroll
            for (int i = 0; i < 4; i++) a[i] = As[kk][ty*4 + i];
            #pragma unroll
            for (int j = 0; j < 4; j++) bb[j] = Bs[kk][tx*4 + j];
            #pragma unroll
            for (int i = 0; i < 4; i++)
                #pragma unroll
                for (int j = 0; j < 4; j++)
                    acc[i][j] = fmaf(a[i], bb[j], acc[i][j]);
        }
        __syncthreads();
    }
    #pragma unroll
    for (int i = 0; i < 4; i++) {
        int r = rowBase + ty*4 + i;
        #pragma unroll
        for (int j = 0; j < 4; j++) {
            int col = colBase + tx*4 + j;
            if (col < N) {
                float v = acc[i][j];
                if (bias)  v += bias[col];
                if (act)   v = silu_f(v);
                if (resid) v += resid[(size_t)r*N + col];
                C[(size_t)r*ldc + col] = v;
            }
        }
    }
}

// ---------------- edge kernel: warp = node, lane = edge ----------------
// smem: sW2[16][544] + sWf[9][544] + Wc1[1024] + bc1[64] + wc2[64] + be2[16]
#define SM_W2    0
#define SM_WF    (16*EDIMP)
#define SM_WC1   (25*EDIMP)
#define SM_BC1   (SM_WC1 + 1024)
#define SM_WC2   (SM_BC1 + 64)
#define SM_BE2   (SM_WC2 + 64)
#define SM_TOTAL_FLOATS (SM_BE2 + 16)
#define EDGE_SMEM_BYTES (SM_TOTAL_FLOATS * 4)

__global__ __launch_bounds__(256, 2) void edge_kernel(
    const float* __restrict__ coors,
    const float* __restrict__ We2,  const float* __restrict__ be2,
    const float* __restrict__ Wc1,  const float* __restrict__ bc1,
    const float* __restrict__ Wc2,  const float* __restrict__ bc2,
    const float* __restrict__ We1,
    float* __restrict__ out_coors)
{
    extern __shared__ float sm[];
    float* sW2  = sm + SM_W2;    // [16][544] row m contiguous in x
    float* sWf  = sm + SM_WF;    // [9][544]
    float* sWc1 = sm + SM_WC1;   // [16][64]
    float* sBc1 = sm + SM_BC1;
    float* sWc2 = sm + SM_WC2;
    float* sBe2 = sm + SM_BE2;

    const int tid = threadIdx.x, lane = tid & 31, w = tid >> 5;
    const int b = blockIdx.y;
    const int i = blockIdx.x * 8 + w;
    const int gi = b*NPTS + i;

    // cooperative weight staging (zero-pad x >= 530)
    for (int t = tid; t < 16*EDIMP; t += 256) {
        int m = t / EDIMP, x = t % EDIMP;
        sW2[t] = (x < EDIM) ? We2[x*16 + m] : 0.0f;
    }
    for (int t = tid; t < 9*EDIMP; t += 256) {
        int r = t / EDIMP, x = t % EDIMP;
        sWf[t] = (x < EDIM) ? We1[(256 + r)*EDIM + x] : 0.0f;
    }
    for (int t = tid; t < 1024; t += 256) sWc1[t] = Wc1[t];
    if (tid < 64) { sBc1[tid] = bc1[tid]; sWc2[tid] = Wc2[tid]; }
    if (tid < 16) sBe2[tid] = be2[tid];
    __syncthreads();

    const float bc2v = bc2[0];

    // this lane's edge
    const int   j = g_knn_idx [gi*KNBR + lane];
    const float d = g_knn_dist[gi*KNBR + lane];
    float f[9];
    {
        const float invs[4] = {1.0f, 0.5f, 0.25f, 0.125f};
        #pragma unroll
        for (int r = 0; r < 4; r++) {
            float sv, cv;
            sincosf(d * invs[r], &sv, &cv);
            f[r] = sv; f[4 + r] = cv;
        }
        f[8] = d;
    }

    const float4* Gp = (const float4*)(g_G + (size_t)gi*EDIMP);                 // broadcast
    const float4* Hp = (const float4*)(g_H + ((size_t)b*NPTS + j)*EDIMP);       // per-lane row

    float acc[16] = {};
    #pragma unroll 2
    for (int c = 0; c < EDIMP/4; c++) {
        float4 g4 = __ldg(Gp + c);
        float4 h4 = __ldg(Hp + c);
        float t0 = g4.x + h4.x, t1 = g4.y + h4.y, t2 = g4.z + h4.z, t3 = g4.w + h4.w;
        #pragma unroll
        for (int r = 0; r < 9; r++) {
            float4 wf = *(const float4*)&sWf[r*EDIMP + c*4];   // broadcast LDS
            t0 = fmaf(f[r], wf.x, t0);
            t1 = fmaf(f[r], wf.y, t1);
            t2 = fmaf(f[r], wf.z, t2);
            t3 = fmaf(f[r], wf.w, t3);
        }
        float s0 = silu_f(t0), s1 = silu_f(t1), s2 = silu_f(t2), s3 = silu_f(t3);
        #pragma unroll
        for (int m = 0; m < 16; m++) {
            float4 wm = *(const float4*)&sW2[m*EDIMP + c*4];   // broadcast LDS
            acc[m] = fmaf(s0, wm.x, fmaf(s1, wm.y, fmaf(s2, wm.z, fmaf(s3, wm.w, acc[m]))));
        }
    }

    // m_ij for this edge (registers)
    float mij[16];
    #pragma unroll
    for (int m = 0; m < 16; m++) mij[m] = silu_f(acc[m] + sBe2[m]);

    // m_i = sum over edges (lanes); lane m writes component m
    #pragma unroll
    for (int m = 0; m < 16; m++) {
        float v = mij[m];
        #pragma unroll
        for (int off = 16; off > 0; off >>= 1)
            v += __shfl_xor_sync(0xffffffffu, v, off);
        if (lane == m) g_mi[(size_t)gi*MD + m] = v;
    }

    // coors MLP per edge: 16 -> 64 (silu) -> 1
    float cw = 0.0f;
    #pragma unroll 4
    for (int hh = 0; hh < 64; hh++) {
        float v = sBc1[hh];
        #pragma unroll
        for (int m = 0; m < 16; m++)
            v = fmaf(mij[m], sWc1[m*64 + hh], v);
        cw = fmaf(silu_f(v), sWc2[hh], cw);
    }
    cw += bc2v;

    // coors_out = sum_e cw_e * (c_i - c_je) + c_i
    {
        const float ci0 = coors[(size_t)gi*3+0];
        const float ci1 = coors[(size_t)gi*3+1];
        const float ci2 = coors[(size_t)gi*3+2];
        const float* cj = coors + ((size_t)b*NPTS + j)*3;
        float rx = cw * (ci0 - cj[0]);
        float ry = cw * (ci1 - cj[1]);
        float rz = cw * (ci2 - cj[2]);
        #pragma unroll
        for (int off = 16; off > 0; off >>= 1) {
            rx += __shfl_xor_sync(0xffffffffu, rx, off);
            ry += __shfl_xor_sync(0xffffffffu, ry, off);
            rz += __shfl_xor_sync(0xffffffffu, rz, off);
        }
        if (lane == 0) {
            out_coors[(size_t)gi*3+0] = rx + ci0;
            out_coors[(size_t)gi*3+1] = ry + ci1;
            out_coors[(size_t)gi*3+2] = rz + ci2;
        }
    }
}

// ---------------- assemble X = [feats | m_i] ----------------
__global__ void assemble_x(const float* __restrict__ feats)
{
    int t = blockIdx.x*blockDim.x + threadIdx.x;
    const int total = NROWS*(DIM+MD);
    if (t < total) {
        int r = t / (DIM+MD), c = t % (DIM+MD);
        g_X[t] = (c < DIM) ? feats[(size_t)r*DIM + c] : g_mi[(size_t)r*MD + (c - DIM)];
    }
}

// ---------------- host launcher ----------------
extern "C" void kernel_launch(void* const* d_in, const int* in_sizes, int n_in,
                              void* d_out, int out_size)
{
    const float* feats = (const float*)d_in[0];
    const float* coors = (const float*)d_in[1];
    const float* We1   = (const float*)d_in[2];
    const float* be1   = (const float*)d_in[3];
    const float* We2   = (const float*)d_in[4];
    const float* be2   = (const float*)d_in[5];
    const float* Wc1   = (const float*)d_in[6];
    const float* bc1   = (const float*)d_in[7];
    const float* Wc2   = (const float*)d_in[8];
    const float* bc2   = (const float*)d_in[9];
    const float* Wn1   = (const float*)d_in[10];
    const float* bn1   = (const float*)d_in[11];
    const float* Wn2   = (const float*)d_in[12];
    const float* bn2   = (const float*)d_in[13];

    float* out       = (float*)d_out;
    float* out_node  = out;                              // (b, n, 128)
    float* out_coors = out + (size_t)NROWS*DIM;          // (b, n, 3)

    float *G, *H, *X, *Hn;
    cudaGetSymbolAddress((void**)&G,  g_G);
    cudaGetSymbolAddress((void**)&H,  g_H);
    cudaGetSymbolAddress((void**)&X,  g_X);
    cudaGetSymbolAddress((void**)&Hn, g_Hn);

    // 1) KNN
    knn_kernel<<<dim3(NPTS, BATCH), 256>>>(coors);

    // 2) G = feats @ We1[0:128] + be1 ; H = feats @ We1[128:256]  (ldc = EDIMP, pads stay 0)
    dim3 gGH((EDIM + 63)/64, NROWS/64);
    sgemm_kernel<<<gGH, 256>>>(feats, We1,            be1,     nullptr, G, NROWS, EDIM, DIM, 0, EDIMP);
    sgemm_kernel<<<gGH, 256>>>(feats, We1 + 128*EDIM, nullptr, nullptr, H, NROWS, EDIM, DIM, 0, EDIMP);

    // 3) edge kernel (warp = node, lane = edge)
    cudaFuncSetAttribute(edge_kernel, cudaFuncAttributeMaxDynamicSharedMemorySize, EDGE_SMEM_BYTES);
    edge_kernel<<<dim3(NPTS/8, BATCH), 256, EDGE_SMEM_BYTES>>>(
        coors, We2, be2, Wc1, bc1, Wc2, bc2, We1, out_coors);

    // 4) node MLP
    {
        int total = NROWS*(DIM+MD);
        assemble_x<<<(total + 255)/256, 256>>>(feats);
    }
    sgemm_kernel<<<dim3((2*DIM + 63)/64, NROWS/64), 256>>>(X,  Wn1, bn1, nullptr, Hn,       NROWS, 2*DIM, DIM+MD, 1, 2*DIM);
    sgemm_kernel<<<dim3((DIM   + 63)/64, NROWS/64), 256>>>(Hn, Wn2, bn2, feats,   out_node, NROWS, DIM,   2*DIM,  0, DIM);
}

// round 5
// speedup vs baseline: 1.5051x; 1.0225x over previous
#include <cuda_runtime.h>
#include <math.h>
#include <float.h>
#include <stdint.h>

#define BATCH 2
#define NPTS  4096
#define DIM   128
#define MD    16
#define KNBR  32
#define EDIM  530              // 2*EDGE_IN
#define EDIMP 544              // padded to 17*32
#define NROWS (BATCH*NPTS)     // 8192

// ---------------- scratch (device globals; zero-initialized at load) ----------------
__device__ float g_G [NROWS*EDIMP];   // padded cols stay zero (never written)
__device__ float g_H [NROWS*EDIMP];
__device__ float g_mi[NROWS*MD];
__device__ float g_Hn[NROWS*(2*DIM)];
__device__ float g_knn_dist[NROWS*KNBR];
__device__ int   g_knn_idx [NROWS*KNBR];

// fast SiLU: MUFU.EX2 + MUFU.RCP, rel err ~1e-6 (threshold is 1e-3)
__device__ __forceinline__ float silu_f(float x){
    return __fdividef(x, 1.0f + __expf(-x));
}

// ---------------- kernel 1: exact KNN ----------------
// stage 1: per-warp register top-32 (exact (dist,index) lexicographic order,
// distances computed with reference-matching __fmul_rn/__fadd_rn).
// stage 2: 256-element bitonic sort of packed (dist,idx) uint64 keys — distances
// are >= 0, so IEEE bits order == float order and the packed key sorts
// lexicographically, matching jax.lax.top_k's stable tie-break.
__global__ __launch_bounds__(256) void knn_kernel(const float* __restrict__ coors)
{
    __shared__ unsigned long long ck[256];
    const int b = blockIdx.y, i = blockIdx.x, tid = threadIdx.x;
    const int lane = tid & 31, w = tid >> 5;
    const float* cb = coors + (size_t)b*NPTS*3;
    const float cx = cb[i*3+0], cy = cb[i*3+1], cz = cb[i*3+2];

    float dl[16];
    const int jbase = w*512 + lane;
    #pragma unroll
    for (int t = 0; t < 16; t++) {
        int j = jbase + t*32;
        float dx = cx - cb[j*3+0];
        float dy = cy - cb[j*3+1];
        float dz = cz - cb[j*3+2];
        dl[t] = __fadd_rn(__fadd_rn(__fmul_rn(dx,dx), __fmul_rn(dy,dy)), __fmul_rn(dz,dz));
    }

    for (int k = 0; k < KNBR; k++) {
        float best = FLT_MAX; int bt = 0;
        #pragma unroll
        for (int t = 0; t < 16; t++)
            if (dl[t] < best) { best = dl[t]; bt = t; }
        int bj = jbase + bt*32;
        float v = best; int jj = (best < FLT_MAX) ? bj : 0x7fffffff;
        #pragma unroll
        for (int off = 16; off > 0; off >>= 1) {
            float v2 = __shfl_xor_sync(0xffffffffu, v, off);
            int   j2 = __shfl_xor_sync(0xffffffffu, jj, off);
            if (v2 < v || (v2 == v && j2 < jj)) { v = v2; jj = j2; }
        }
        if (jj == bj) dl[bt] = FLT_MAX;
        if (lane == 0)
            ck[w*32 + k] = ((unsigned long long)__float_as_uint(v) << 32) | (unsigned int)jj;
    }
    __syncthreads();

    // bitonic sort 256 keys ascending
    #pragma unroll 1
    for (int k = 2; k <= 256; k <<= 1) {
        #pragma unroll 1
        for (int j = k >> 1; j > 0; j >>= 1) {
            int p = tid ^ j;
            if (p > tid) {
                bool asc = ((tid & k) == 0);
                unsigned long long a = ck[tid], bb = ck[p];
                if ((a > bb) == asc) { ck[tid] = bb; ck[p] = a; }
            }
            __syncthreads();
        }
    }
    if (tid < KNBR) {
        unsigned long long key = ck[tid];
        const int gi = b*NPTS + i;
        g_knn_dist[gi*KNBR + tid] = __uint_as_float((unsigned int)(key >> 32));
        g_knn_idx [gi*KNBR + tid] = (int)(unsigned int)(key & 0xffffffffu);
    }
}

// ---------------- generic tiled SGEMM: C = act(A@B + bias) (+resid), ldc ----------------
__global__ __launch_bounds__(256) void sgemm_kernel(
    const float* __restrict__ A, const float* __restrict__ B,
    const float* __restrict__ bias, const float* __restrict__ resid,
    float* __restrict__ C, int M, int N, int K, int act, int ldc)
{
    __shared__ float As[16][65];
    __shared__ float Bs[16][68];
    const int tid = threadIdx.x;
    const int tx = tid & 15, ty = tid >> 4;
    const int rowBase = blockIdx.y * 64, colBase = blockIdx.x * 64;
    const int aK = tid & 15, aRow = tid >> 4;
    const int bCol = tid & 63, bK = tid >> 6;
    float acc[4][4] = {};

    for (int k0 = 0; k0 < K; k0 += 16) {
        #pragma unroll
        for (int s = 0; s < 4; s++) {
            int r = aRow + s*16;
            As[aK][r] = A[(size_t)(rowBase + r)*K + k0 + aK];
        }
        #pragma unroll
        for (int s = 0; s < 4; s++) {
            int kk = bK + s*4;
            int col = colBase + bCol;
            Bs[kk][bCol] = (col < N) ? B[(size_t)(k0 + kk)*N + col] : 0.0f;
        }
        __syncthreads();
        #pragma unroll
        for (int kk = 0; kk < 16; kk++) {
            float a[4], bb[4];
            #pragma unroll
            for (int i = 0; i < 4; i++) a[i] = As[kk][ty*4 + i];
            #pragma unroll
            for (int j = 0; j < 4; j++) bb[j] = Bs[kk][tx*4 + j];
            #pragma unroll
            for (int i = 0; i < 4; i++)
                #pragma unroll
                for (int j = 0; j < 4; j++)
                    acc[i][j] = fmaf(a[i], bb[j], acc[i][j]);
        }
        __syncthreads();
    }
    #pragma unroll
    for (int i = 0; i < 4; i++) {
        int r = rowBase + ty*4 + i;
        #pragma unroll
        for (int j = 0; j < 4; j++) {
            int col = colBase + tx*4 + j;
            if (col < N) {
                float v = acc[i][j];
                if (bias)  v += bias[col];
                if (act)   v = silu_f(v);
                if (resid) v += resid[(size_t)r*N + col];
                C[(size_t)r*ldc + col] = v;
            }
        }
    }
}

// ------- node-MLP layer 1 GEMM with A = [feats | m_i] fused (K = 144) -------
__global__ __launch_bounds__(256) void gemm_node1(
    const float* __restrict__ feats, const float* __restrict__ B,
    const float* __restrict__ bias, float* __restrict__ C, int N)
{
    const int K = DIM + MD;
    __shared__ float As[16][65];
    __shared__ float Bs[16][68];
    const int tid = threadIdx.x;
    const int tx = tid & 15, ty = tid >> 4;
    const int rowBase = blockIdx.y * 64, colBase = blockIdx.x * 64;
    const int aK = tid & 15, aRow = tid >> 4;
    const int bCol = tid & 63, bK = tid >> 6;
    float acc[4][4] = {};

    for (int k0 = 0; k0 < K; k0 += 16) {
        #pragma unroll
        for (int s = 0; s < 4; s++) {
            int r = rowBase + aRow + s*16;
            int kk = k0 + aK;
            As[aK][aRow + s*16] = (kk < DIM) ? feats[(size_t)r*DIM + kk]
                                             : g_mi[(size_t)r*MD + (kk - DIM)];
        }
        #pragma unroll
        for (int s = 0; s < 4; s++) {
            int kk = bK + s*4;
            int col = colBase + bCol;
            Bs[kk][bCol] = B[(size_t)(k0 + kk)*N + col];
        }
        __syncthreads();
        #pragma unroll
        for (int kk = 0; kk < 16; kk++) {
            float a[4], bb[4];
            #pragma unroll
            for (int i = 0; i < 4; i++) a[i] = As[kk][ty*4 + i];
            #pragma unroll
            for (int j = 0; j < 4; j++) bb[j] = Bs[kk][tx*4 + j];
            #pragma unroll
            for (int i = 0; i < 4; i++)
                #pragma unroll
                for (int j = 0; j < 4; j++)
                    acc[i][j] = fmaf(a[i], bb[j], acc[i][j]);
        }
        __syncthreads();
    }
    #pragma unroll
    for (int i = 0; i < 4; i++) {
        int r = rowBase + ty*4 + i;
        #pragma unroll
        for (int j = 0; j < 4; j++) {
            int col = colBase + tx*4 + j;
            float v = acc[i][j] + bias[col];
            C[(size_t)r*N + col] = silu_f(v);
        }
    }
}

// ---------------- edge kernel: 4 warps, 2 nodes/warp, lane = edge ----------------
// smem layout (floats)
#define SM_W2    0
#define SM_WF    (16*EDIMP)
#define SM_WC1   (25*EDIMP)
#define SM_BC1   (SM_WC1 + 1024)
#define SM_WC2   (SM_BC1 + 64)
#define SM_BE2   (SM_WC2 + 64)
#define SM_HS    (SM_BE2 + 16)
#define HS_PITCH 36                     // 32 cols + 4 pad (bank-conflict-free)
#define HS_WARP  (2*32*HS_PITCH)        // 2 nodes x 32 rows x 36
#define SM_TOTAL_FLOATS (SM_HS + 4*HS_WARP)
#define EDGE_SMEM_BYTES (SM_TOTAL_FLOATS * 4)

__global__ __launch_bounds__(128, 2) void edge_kernel(
    const float* __restrict__ coors,
    const float* __restrict__ We2,  const float* __restrict__ be2,
    const float* __restrict__ Wc1,  const float* __restrict__ bc1,
    const float* __restrict__ Wc2,  const float* __restrict__ bc2,
    const float* __restrict__ We1,
    float* __restrict__ out_coors)
{
    extern __shared__ float sm[];
    float* sW2  = sm + SM_W2;    // [16][544]
    float* sWf  = sm + SM_WF;    // [9][544]
    float* sWc1 = sm + SM_WC1;   // [16][64]
    float* sBc1 = sm + SM_BC1;
    float* sWc2 = sm + SM_WC2;
    float* sBe2 = sm + SM_BE2;

    const int tid = threadIdx.x, lane = tid & 31, w = tid >> 5;
    const int b = blockIdx.y;
    const int iA = blockIdx.x * 8 + w*2;
    const int giA = b*NPTS + iA;
    const int giB = giA + 1;

    // cooperative weight staging (128 threads)
    for (int t = tid; t < 16*EDIMP; t += 128) {
        int m = t / EDIMP, x = t % EDIMP;
        sW2[t] = (x < EDIM) ? We2[x*16 + m] : 0.0f;
    }
    for (int t = tid; t < 9*EDIMP; t += 128) {
        int r = t / EDIMP, x = t % EDIMP;
        sWf[t] = (x < EDIM) ? We1[(256 + r)*EDIM + x] : 0.0f;
    }
    for (int t = tid; t < 1024; t += 128) sWc1[t] = Wc1[t];
    if (tid < 64) { sBc1[tid] = bc1[tid]; sWc2[tid] = Wc2[tid]; }
    if (tid < 16) sBe2[tid] = be2[tid];
    __syncthreads();

    const float bc2v = bc2[0];

    // this lane's edge for each of the two nodes
    const int   jA = g_knn_idx [giA*KNBR + lane];
    const float dA = g_knn_dist[giA*KNBR + lane];
    const int   jB = g_knn_idx [giB*KNBR + lane];
    const float dB = g_knn_dist[giB*KNBR + lane];
    float fA[9], fB[9];
    {
        const float invs[4] = {1.0f, 0.5f, 0.25f, 0.125f};
        #pragma unroll
        for (int r = 0; r < 4; r++) {
            float sv, cv;
            sincosf(dA * invs[r], &sv, &cv); fA[r] = sv; fA[4+r] = cv;
            sincosf(dB * invs[r], &sv, &cv); fB[r] = sv; fB[4+r] = cv;
        }
        fA[8] = dA; fB[8] = dB;
    }

    const float* Hb = g_H + (size_t)b*NPTS*EDIMP;
    const float* GA = g_G + (size_t)giA*EDIMP;
    const float* GB = g_G + (size_t)giB*EDIMP;
    float* hsA = sm + SM_HS + w*HS_WARP;       // [32][36]
    float* hsB = hsA + 32*HS_PITCH;

    float accA[16] = {}, accB[16] = {};

    const int rr = (lane >> 3);          // row sub-index within 4-row group
    const int cc = (lane & 7) * 4;       // float col offset within chunk

    #pragma unroll 1
    for (int ch = 0; ch < 17; ch++) {
        const int c0 = ch * 32;
        __syncwarp();
        // coalesced staging: instr i loads rows 4i..4i+3, 8 lanes per full 128B line
        #pragma unroll
        for (int i = 0; i < 8; i++) {
            int row = i*4 + rr;
            int jrA = __shfl_sync(0xffffffffu, jA, row);
            int jrB = __shfl_sync(0xffffffffu, jB, row);
            float4 va = __ldg((const float4*)(Hb + (size_t)jrA*EDIMP + c0 + cc));
            float4 vb = __ldg((const float4*)(Hb + (size_t)jrB*EDIMP + c0 + cc));
            *(float4*)&hsA[row*HS_PITCH + cc] = va;
            *(float4*)&hsB[row*HS_PITCH + cc] = vb;
        }
        __syncwarp();
        #pragma unroll
        for (int xs = 0; xs < 8; xs++) {
            const int x = c0 + xs*4;
            float4 g4a = __ldg((const float4*)(GA + x));   // broadcast
            float4 g4b = __ldg((const float4*)(GB + x));
            float4 h4a = *(const float4*)&hsA[lane*HS_PITCH + xs*4];
            float4 h4b = *(const float4*)&hsB[lane*HS_PITCH + xs*4];
            float ta0 = g4a.x + h4a.x, ta1 = g4a.y + h4a.y, ta2 = g4a.z + h4a.z, ta3 = g4a.w + h4a.w;
            float tb0 = g4b.x + h4b.x, tb1 = g4b.y + h4b.y, tb2 = g4b.z + h4b.z, tb3 = g4b.w + h4b.w;
            #pragma unroll
            for (int r = 0; r < 9; r++) {
                float4 wf = *(const float4*)&sWf[r*EDIMP + x];   // broadcast LDS
                ta0 = fmaf(fA[r], wf.x, ta0); ta1 = fmaf(fA[r], wf.y, ta1);
                ta2 = fmaf(fA[r], wf.z, ta2); ta3 = fmaf(fA[r], wf.w, ta3);
                tb0 = fmaf(fB[r], wf.x, tb0); tb1 = fmaf(fB[r], wf.y, tb1);
                tb2 = fmaf(fB[r], wf.z, tb2); tb3 = fmaf(fB[r], wf.w, tb3);
            }
            float sa0 = silu_f(ta0), sa1 = silu_f(ta1), sa2 = silu_f(ta2), sa3 = silu_f(ta3);
            float sb0 = silu_f(tb0), sb1 = silu_f(tb1), sb2 = silu_f(tb2), sb3 = silu_f(tb3);
            #pragma unroll
            for (int m = 0; m < 16; m++) {
                float4 wm = *(const float4*)&sW2[m*EDIMP + x];   // broadcast LDS
                accA[m] = fmaf(sa0, wm.x, fmaf(sa1, wm.y, fmaf(sa2, wm.z, fmaf(sa3, wm.w, accA[m]))));
                accB[m] = fmaf(sb0, wm.x, fmaf(sb1, wm.y, fmaf(sb2, wm.z, fmaf(sb3, wm.w, accB[m]))));
            }
        }
    }

    // ---------------- epilogue, per node ----------------
    #pragma unroll 1
    for (int nn = 0; nn < 2; nn++) {
        const int gi = nn ? giB : giA;
        const int j  = nn ? jB  : jA;
        float* acc   = nn ? accB : accA;

        float mij[16];
        #pragma unroll
        for (int m = 0; m < 16; m++) mij[m] = silu_f(acc[m] + sBe2[m]);

        // m_i = sum over lanes
        #pragma unroll
        for (int m = 0; m < 16; m++) {
            float v = mij[m];
            #pragma unroll
            for (int off = 16; off > 0; off >>= 1)
                v += __shfl_xor_sync(0xffffffffu, v, off);
            if (lane == m) g_mi[(size_t)gi*MD + m] = v;
        }

        // coors MLP per edge: 16 -> 64 (silu) -> 1
        float cw = 0.0f;
        #pragma unroll 4
        for (int hh = 0; hh < 64; hh++) {
            float v = sBc1[hh];
            #pragma unroll
            for (int m = 0; m < 16; m++)
                v = fmaf(mij[m], sWc1[m*64 + hh], v);
            cw = fmaf(silu_f(v), sWc2[hh], cw);
        }
        cw += bc2v;

        const float ci0 = coors[(size_t)gi*3+0];
        const float ci1 = coors[(size_t)gi*3+1];
        const float ci2 = coors[(size_t)gi*3+2];
        const float* cj = coors + ((size_t)b*NPTS + j)*3;
        float rx = cw * (ci0 - cj[0]);
        float ry = cw * (ci1 - cj[1]);
        float rz = cw * (ci2 - cj[2]);
        #pragma unroll
        for (int off = 16; off > 0; off >>= 1) {
            rx += __shfl_xor_sync(0xffffffffu, rx, off);
            ry += __shfl_xor_sync(0xffffffffu, ry, off);
            rz += __shfl_xor_sync(0xffffffffu, rz, off);
        }
        if (lane == 0) {
            out_coors[(size_t)gi*3+0] = rx + ci0;
            out_coors[(size_t)gi*3+1] = ry + ci1;
            out_coors[(size_t)gi*3+2] = rz + ci2;
        }
    }
}

// ---------------- host launcher ----------------
extern "C" void kernel_launch(void* const* d_in, const int* in_sizes, int n_in,
                              void* d_out, int out_size)
{
    const float* feats = (const float*)d_in[0];
    const float* coors = (const float*)d_in[1];
    const float* We1   = (const float*)d_in[2];
    const float* be1   = (const float*)d_in[3];
    const float* We2   = (const float*)d_in[4];
    const float* be2   = (const float*)d_in[5];
    const float* Wc1   = (const float*)d_in[6];
    const float* bc1   = (const float*)d_in[7];
    const float* Wc2   = (const float*)d_in[8];
    const float* bc2   = (const float*)d_in[9];
    const float* Wn1   = (const float*)d_in[10];
    const float* bn1   = (const float*)d_in[11];
    const float* Wn2   = (const float*)d_in[12];
    const float* bn2   = (const float*)d_in[13];

    float* out       = (float*)d_out;
    float* out_node  = out;                              // (b, n, 128)
    float* out_coors = out + (size_t)NROWS*DIM;          // (b, n, 3)

    float *G, *H, *Hn;
    cudaGetSymbolAddress((void**)&G,  g_G);
    cudaGetSymbolAddress((void**)&H,  g_H);
    cudaGetSymbolAddress((void**)&Hn, g_Hn);

    // 1) KNN
    knn_kernel<<<dim3(NPTS, BATCH), 256>>>(coors);

    // 2) G = feats @ We1[0:128] + be1 ; H = feats @ We1[128:256]  (ldc = EDIMP)
    dim3 gGH((EDIM + 63)/64, NROWS/64);
    sgemm_kernel<<<gGH, 256>>>(feats, We1,            be1,     nullptr, G, NROWS, EDIM, DIM, 0, EDIMP);
    sgemm_kernel<<<gGH, 256>>>(feats, We1 + 128*EDIM, nullptr, nullptr, H, NROWS, EDIM, DIM, 0, EDIMP);

    // 3) edge kernel (4 warps/block, 2 nodes/warp, lane = edge)
    cudaFuncSetAttribute(edge_kernel, cudaFuncAttributeMaxDynamicSharedMemorySize, EDGE_SMEM_BYTES);
    edge_kernel<<<dim3(NPTS/8, BATCH), 128, EDGE_SMEM_BYTES>>>(
        coors, We2, be2, Wc1, bc1, Wc2, bc2, We1, out_coors);

    // 4) node MLP (layer 1 fuses [feats | m_i] concat)
    gemm_node1<<<dim3((2*DIM)/64, NROWS/64), 256>>>(feats, Wn1, bn1, Hn, 2*DIM);
    sgemm_kernel<<<dim3(DIM/64, NROWS/64), 256>>>(Hn, Wn2, bn2, feats, out_node, NROWS, DIM, 2*DIM, 0, DIM);
}